// round 3
// baseline (speedup 1.0000x reference)
#include <cuda_runtime.h>

#define BB 32
#define CC 256
#define SS 1024
static const size_t BSC = (size_t)BB * SS * CC;   // 8388608

// scratch: QL, KL, VH(->W1), QH, KH, VL(->W2), O1, O2  (each [B,S,C] fp32)
__device__ float g_scratch[8ull * 8388608ull];

__device__ __forceinline__ float fexp(float x) {
    x = fmaxf(x, -80.0f);
    float z  = x * 1.44269504f;
    float t  = z + 12582912.0f;
    float fi = t - 12582912.0f;
    float f  = z - fi;
    float y  = f * 0.69314718f;
    float p  = 1.0f + y * (1.0f + y * (0.5f + y * (0.16666667f +
               y * (0.041666667f + y * 0.0083333333f))));
    return p * __int_as_float(((int)fi + 127) << 23);
}

// ---------------- router ----------------
__global__ void router_kernel(const float* __restrict__ lidar, const float* __restrict__ hsi,
                              const float* __restrict__ w1, const float* __restrict__ b1,
                              const float* __restrict__ w2, const float* __restrict__ b2,
                              float* __restrict__ path) {
    __shared__ float g[512];
    __shared__ float hid[128];
    int b = blockIdx.x, t = threadIdx.x;
    const float* src = (t < 256) ? (lidar + ((size_t)b * CC + t) * SS)
                                 : (hsi   + ((size_t)b * CC + (t - 256)) * SS);
    float s = 0.f;
    for (int i = 0; i < SS; i += 4) {
        float4 v = *(const float4*)&src[i];
        s += v.x + v.y + v.z + v.w;
    }
    g[t] = s * (1.0f / 1024.0f);
    __syncthreads();
    if (t < 128) {
        float acc = b1[t];
        const float* wr = w1 + (size_t)t * 512;
        for (int i = 0; i < 512; i++) acc = fmaf(g[i], wr[i], acc);
        hid[t] = fmaxf(acc, 0.f);
    }
    __syncthreads();
    if (t < 4) {
        float acc = b2[t];
        const float* wr = w2 + (size_t)t * 128;
        for (int i = 0; i < 128; i++) acc = fmaf(hid[i], wr[i], acc);
        path[b * 4 + t] = 1.0f / (1.0f + __expf(-acc));
    }
}

// ---------------- projection: out[b,s,o] = sum_c X[b,c,s]*Wm[o,c] + bias[o] ----
__global__ __launch_bounds__(256) void proj_kernel(
        const float* __restrict__ X, const float* __restrict__ Wm,
        const float* __restrict__ bias, float* __restrict__ out) {
    __shared__ __align__(16) float As[16][132];
    __shared__ __align__(16) float Bs[16][132];
    int b = blockIdx.z, s0 = blockIdx.x * 128, o0 = blockIdx.y * 128;
    int tid = threadIdx.x;
    int ts = tid >> 4, to = tid & 15;
    const float* Xb = X + (size_t)b * CC * SS;

    float acc[8][8];
#pragma unroll
    for (int i = 0; i < 8; i++)
#pragma unroll
        for (int j = 0; j < 8; j++) acc[i][j] = 0.f;

    for (int c0 = 0; c0 < 256; c0 += 16) {
#pragma unroll
        for (int u = 0; u < 2; u++) {
            int idx = u * 256 + tid;
            int kk = idx >> 5, s4 = (idx & 31) << 2;
            *(float4*)&As[kk][s4] = *(const float4*)&Xb[(size_t)(c0 + kk) * SS + s0 + s4];
        }
#pragma unroll
        for (int u = 0; u < 2; u++) {
            int idx = u * 256 + tid;
            int oo = idx >> 2, kq = (idx & 3) << 2;
            float4 w = *(const float4*)&Wm[(size_t)(o0 + oo) * 256 + c0 + kq];
            Bs[kq + 0][oo] = w.x; Bs[kq + 1][oo] = w.y;
            Bs[kq + 2][oo] = w.z; Bs[kq + 3][oo] = w.w;
        }
        __syncthreads();
#pragma unroll
        for (int kk = 0; kk < 16; kk++) {
            float4 a0 = *(float4*)&As[kk][ts * 4];
            float4 a1 = *(float4*)&As[kk][64 + ts * 4];
            float4 b0 = *(float4*)&Bs[kk][to * 4];
            float4 b1v = *(float4*)&Bs[kk][64 + to * 4];
            float av[8] = {a0.x, a0.y, a0.z, a0.w, a1.x, a1.y, a1.z, a1.w};
            float bv[8] = {b0.x, b0.y, b0.z, b0.w, b1v.x, b1v.y, b1v.z, b1v.w};
#pragma unroll
            for (int i = 0; i < 8; i++)
#pragma unroll
                for (int j = 0; j < 8; j++)
                    acc[i][j] = fmaf(av[i], bv[j], acc[i][j]);
        }
        __syncthreads();
    }
    float bvals[8];
#pragma unroll
    for (int j = 0; j < 8; j++)
        bvals[j] = bias[o0 + ((j < 4) ? to * 4 + j : 64 + to * 4 + (j - 4))];
#pragma unroll
    for (int i = 0; i < 8; i++) {
        int sr = (i < 4) ? ts * 4 + i : 64 + ts * 4 + (i - 4);
        float* orow = out + ((size_t)b * SS + s0 + sr) * CC + o0;
        *(float4*)&orow[to * 4] = make_float4(acc[i][0] + bvals[0], acc[i][1] + bvals[1],
                                              acc[i][2] + bvals[2], acc[i][3] + bvals[3]);
        *(float4*)&orow[64 + to * 4] = make_float4(acc[i][4] + bvals[4], acc[i][5] + bvals[5],
                                                   acc[i][6] + bvals[6], acc[i][7] + bvals[7]);
    }
}

// ---------------- elementwise a *= b ----------------
__global__ void mul_kernel(float* __restrict__ a, const float* __restrict__ b) {
    size_t i = ((size_t)blockIdx.x * 256 + threadIdx.x) * 4;
    float4 av = *(float4*)&a[i];
    float4 bv = *(const float4*)&b[i];
    av.x *= bv.x; av.y *= bv.y; av.z *= bv.z; av.w *= bv.w;
    *(float4*)&a[i] = av;
}

// ---------------- flash attention: O = softmax(Q K^T) W ----------------
#define QSTR 260
#define PSTR 68
#define ATTN_SMEM ((2 * 64 * QSTR + 64 * PSTR) * 4)

__global__ __launch_bounds__(256) void attn_kernel(
        const float* __restrict__ Qm, const float* __restrict__ Km,
        const float* __restrict__ Wm, float* __restrict__ Om) {
    extern __shared__ float sm[];
    float* Qs = sm;
    float* Ks = sm + 64 * QSTR;
    float* Ps = sm + 2 * 64 * QSTR;
    int b = blockIdx.y, q0 = blockIdx.x * 64;
    int tid = threadIdx.x;
    int tr = tid >> 4, tc = tid & 15;
    const float* Qb = Qm + ((size_t)b * SS + q0) * CC;
    const float* Kb = Km + (size_t)b * SS * CC;
    const float* Wb = Wm + (size_t)b * SS * CC;
    float* Ob = Om + ((size_t)b * SS + q0) * CC;

    for (int idx = tid; idx < 4096; idx += 256) {
        int r = idx >> 6, c4 = (idx & 63) << 2;
        *(float4*)&Qs[r * QSTR + c4] = *(const float4*)&Qb[(size_t)r * CC + c4];
    }
    float O[4][16];
#pragma unroll
    for (int i = 0; i < 4; i++)
#pragma unroll
        for (int c = 0; c < 16; c++) O[i][c] = 0.f;
    float mrow[4] = {-1e30f, -1e30f, -1e30f, -1e30f};
    float lrow[4] = {0.f, 0.f, 0.f, 0.f};
    __syncthreads();

    for (int t0 = 0; t0 < SS; t0 += 64) {
        for (int idx = tid; idx < 4096; idx += 256) {
            int r = idx >> 6, c4 = (idx & 63) << 2;
            *(float4*)&Ks[r * QSTR + c4] = *(const float4*)&Kb[((size_t)t0 + r) * CC + c4];
        }
        __syncthreads();

        float sc[4][4];
#pragma unroll
        for (int i = 0; i < 4; i++)
#pragma unroll
            for (int j = 0; j < 4; j++) sc[i][j] = 0.f;
#pragma unroll 4
        for (int k = 0; k < 256; k += 4) {
            float4 qf[4], kf[4];
#pragma unroll
            for (int i = 0; i < 4; i++) qf[i] = *(float4*)&Qs[(tr * 4 + i) * QSTR + k];
#pragma unroll
            for (int j = 0; j < 4; j++) kf[j] = *(float4*)&Ks[(tc + 16 * j) * QSTR + k];
#pragma unroll
            for (int i = 0; i < 4; i++)
#pragma unroll
                for (int j = 0; j < 4; j++)
                    sc[i][j] = fmaf(qf[i].x, kf[j].x, fmaf(qf[i].y, kf[j].y,
                               fmaf(qf[i].z, kf[j].z, fmaf(qf[i].w, kf[j].w, sc[i][j]))));
        }

#pragma unroll
        for (int i = 0; i < 4; i++) {
            float mx = fmaxf(fmaxf(sc[i][0], sc[i][1]), fmaxf(sc[i][2], sc[i][3]));
#pragma unroll
            for (int off = 1; off < 16; off <<= 1)
                mx = fmaxf(mx, __shfl_xor_sync(0xffffffffu, mx, off));
            float mnew  = fmaxf(mrow[i], mx);
            float alpha = fexp(mrow[i] - mnew);
            mrow[i] = mnew;
            float ls = 0.f;
#pragma unroll
            for (int j = 0; j < 4; j++) {
                float p = fexp(sc[i][j] - mnew);
                sc[i][j] = p;
                ls += p;
            }
#pragma unroll
            for (int off = 1; off < 16; off <<= 1)
                ls += __shfl_xor_sync(0xffffffffu, ls, off);
            lrow[i] = lrow[i] * alpha + ls;
#pragma unroll
            for (int c = 0; c < 16; c++) O[i][c] *= alpha;
#pragma unroll
            for (int j = 0; j < 4; j++)
                Ps[(tr * 4 + i) * PSTR + tc + 16 * j] = sc[i][j];
        }
        __syncthreads();  // Ps visible; Ks free

        for (int idx = tid; idx < 4096; idx += 256) {
            int r = idx >> 6, c4 = (idx & 63) << 2;
            *(float4*)&Ks[r * QSTR + c4] = *(const float4*)&Wb[((size_t)t0 + r) * CC + c4];
        }
        __syncthreads();

        // PV: thread owns cols j*64 + tc*4 + e  (j=0..3, e=0..3)
#pragma unroll 2
        for (int t = 0; t < 64; t++) {
            float pv[4];
#pragma unroll
            for (int i = 0; i < 4; i++) pv[i] = Ps[(tr * 4 + i) * PSTR + t];
            const float* wr = &Ks[t * QSTR];
            float4 w0 = *(const float4*)(wr + tc * 4);
            float4 w1 = *(const float4*)(wr + 64 + tc * 4);
            float4 w2 = *(const float4*)(wr + 128 + tc * 4);
            float4 w3 = *(const float4*)(wr + 192 + tc * 4);
            float wv[16] = {w0.x, w0.y, w0.z, w0.w, w1.x, w1.y, w1.z, w1.w,
                            w2.x, w2.y, w2.z, w2.w, w3.x, w3.y, w3.z, w3.w};
#pragma unroll
            for (int i = 0; i < 4; i++)
#pragma unroll
                for (int c = 0; c < 16; c++)
                    O[i][c] = fmaf(pv[i], wv[c], O[i][c]);
        }
        __syncthreads();
    }

#pragma unroll
    for (int i = 0; i < 4; i++) {
        float inv = 1.0f / lrow[i];
        float* orow = Ob + (size_t)(tr * 4 + i) * CC;
#pragma unroll
        for (int j = 0; j < 4; j++)
            *(float4*)&orow[j * 64 + tc * 4] =
                make_float4(O[i][4 * j] * inv, O[i][4 * j + 1] * inv,
                            O[i][4 * j + 2] * inv, O[i][4 * j + 3] * inv);
    }
}

// ---------------- 1x1 conv + residual ----------------
__global__ __launch_bounds__(256) void conv_kernel(
        const float* __restrict__ lo, const float* __restrict__ ho,
        const float* __restrict__ cw, const float* __restrict__ cb,
        const float* __restrict__ x, float* __restrict__ emb) {
    __shared__ __align__(16) float As[16][132];
    __shared__ __align__(16) float Bs[16][132];
    int b = blockIdx.z, s0 = blockIdx.x * 128, o0 = blockIdx.y * 128;
    int tid = threadIdx.x;
    int ts = tid & 15, to = tid >> 4;

    float acc[8][8];
#pragma unroll
    for (int i = 0; i < 8; i++)
#pragma unroll
        for (int j = 0; j < 8; j++) acc[i][j] = 0.f;

    for (int c0 = 0; c0 < 512; c0 += 16) {
        const float* src = (c0 < 256) ? lo : ho;
        int cbase = c0 & 255;
#pragma unroll
        for (int u = 0; u < 2; u++) {
            int idx = u * 256 + tid;
            int ss = idx >> 2, kq = (idx & 3) << 2;
            float4 a = *(const float4*)&src[((size_t)b * SS + s0 + ss) * CC + cbase + kq];
            As[kq + 0][ss] = a.x; As[kq + 1][ss] = a.y;
            As[kq + 2][ss] = a.z; As[kq + 3][ss] = a.w;
        }
#pragma unroll
        for (int u = 0; u < 2; u++) {
            int idx = u * 256 + tid;
            int oo = idx >> 2, kq = (idx & 3) << 2;
            float4 w = *(const float4*)&cw[(size_t)(o0 + oo) * 512 + c0 + kq];
            Bs[kq + 0][oo] = w.x; Bs[kq + 1][oo] = w.y;
            Bs[kq + 2][oo] = w.z; Bs[kq + 3][oo] = w.w;
        }
        __syncthreads();
#pragma unroll
        for (int kk = 0; kk < 16; kk++) {
            float4 a0 = *(float4*)&As[kk][ts * 4];
            float4 a1 = *(float4*)&As[kk][64 + ts * 4];
            float4 b0 = *(float4*)&Bs[kk][to * 4];
            float4 b1v = *(float4*)&Bs[kk][64 + to * 4];
            float av[8] = {a0.x, a0.y, a0.z, a0.w, a1.x, a1.y, a1.z, a1.w};
            float bv[8] = {b0.x, b0.y, b0.z, b0.w, b1v.x, b1v.y, b1v.z, b1v.w};
#pragma unroll
            for (int i = 0; i < 8; i++)
#pragma unroll
                for (int j = 0; j < 8; j++)
                    acc[i][j] = fmaf(av[i], bv[j], acc[i][j]);
        }
        __syncthreads();
    }

#pragma unroll
    for (int j = 0; j < 8; j++) {
        int oc = (j < 4) ? to * 4 + j : 64 + to * 4 + (j - 4);
        float bo = cb[o0 + oc];
        const float* xrow = x   + ((size_t)b * CC + o0 + oc) * SS + s0;
        float*       erow = emb + ((size_t)b * CC + o0 + oc) * SS + s0;
        float4 xv0 = *(const float4*)&xrow[ts * 4];
        float4 xv1 = *(const float4*)&xrow[64 + ts * 4];
        *(float4*)&erow[ts * 4] = make_float4(acc[0][j] + bo + xv0.x, acc[1][j] + bo + xv0.y,
                                              acc[2][j] + bo + xv0.z, acc[3][j] + bo + xv0.w);
        *(float4*)&erow[64 + ts * 4] = make_float4(acc[4][j] + bo + xv1.x, acc[5][j] + bo + xv1.y,
                                                   acc[6][j] + bo + xv1.z, acc[7][j] + bo + xv1.w);
    }
}

extern "C" void kernel_launch(void* const* d_in, const int* in_sizes, int n_in,
                              void* d_out, int out_size) {
    const float* lidar  = (const float*)d_in[0];
    const float* hsi    = (const float*)d_in[1];
    const float* x      = (const float*)d_in[2];
    const float* Wq     = (const float*)d_in[3];
    const float* bq     = (const float*)d_in[4];
    const float* Wk     = (const float*)d_in[5];
    const float* bk     = (const float*)d_in[6];
    const float* Wv     = (const float*)d_in[7];
    const float* bv     = (const float*)d_in[8];
    const float* conv_w = (const float*)d_in[9];
    const float* conv_b = (const float*)d_in[10];
    const float* r_w1   = (const float*)d_in[11];
    const float* r_b1   = (const float*)d_in[12];
    const float* r_w2   = (const float*)d_in[13];
    const float* r_b2   = (const float*)d_in[14];

    float* emb  = (float*)d_out;
    float* path = (float*)d_out + ((size_t)out_size - BB * 4);

    float* scratch = nullptr;
    cudaGetSymbolAddress((void**)&scratch, g_scratch);
    float* QL = scratch + 0 * BSC;
    float* KL = scratch + 1 * BSC;
    float* VH = scratch + 2 * BSC;   // becomes W1 = QL*VH
    float* QH = scratch + 3 * BSC;
    float* KH = scratch + 4 * BSC;
    float* VL = scratch + 5 * BSC;   // becomes W2 = QH*VL
    float* O1 = scratch + 6 * BSC;   // h_emb
    float* O2 = scratch + 7 * BSC;   // l_emb

    static int smem_set = 0;
    if (!smem_set) {
        cudaFuncSetAttribute(attn_kernel, cudaFuncAttributeMaxDynamicSharedMemorySize, ATTN_SMEM);
        smem_set = 1;
    }

    router_kernel<<<BB, 512>>>(lidar, hsi, r_w1, r_b1, r_w2, r_b2, path);

    dim3 pg(8, 2, BB);
    proj_kernel<<<pg, 256>>>(lidar, Wq, bq, QL);
    proj_kernel<<<pg, 256>>>(lidar, Wk, bk, KL);
    proj_kernel<<<pg, 256>>>(hsi,   Wv, bv, VH);
    proj_kernel<<<pg, 256>>>(hsi,   Wq, bq, QH);
    proj_kernel<<<pg, 256>>>(hsi,   Wk, bk, KH);
    proj_kernel<<<pg, 256>>>(lidar, Wv, bv, VL);

    mul_kernel<<<(int)(BSC / 1024), 256>>>(VH, QL);   // W1
    mul_kernel<<<(int)(BSC / 1024), 256>>>(VL, QH);   // W2

    dim3 ag(16, BB);
    attn_kernel<<<ag, 256, ATTN_SMEM>>>(QL, KL, VH, O1);  // h_emb
    attn_kernel<<<ag, 256, ATTN_SMEM>>>(QH, KH, VL, O2);  // l_emb

    dim3 cg(8, 2, BB);
    conv_kernel<<<cg, 256>>>(O2, O1, conv_w, conv_b, x, emb);
}